// round 8
// baseline (speedup 1.0000x reference)
#include <cuda_runtime.h>
#include <cuda_fp16.h>
#include <cstdint>

// Fused int4 group-dequant + GEMM via single-product fp16 mma.sync.
// Round 8: round-7 shell (128x128 tile, 8 warps, 3-stage cp.async, 2 CTA/SM)
// + register fragment double-buffering: ldsm(kk+1) issues before mma(kk),
// hiding the ~30cyc ldmatrix latency behind the mma batch.

namespace {

constexpr int MMAX = 8192, NMAX = 4096, KMAX = 4096;

__device__ __half g_X[(size_t)MMAX * KMAX];
__device__ __half g_W[(size_t)NMAX * KMAX];

constexpr int BM = 128, BN = 128, BK = 64;
constexpr int THREADS = 256;
constexpr int ROWB = 144;                 // 64 fp16 = 128B + 16B pad
constexpr int A_OFF = 0;
constexpr int B_OFF = BM * ROWB;          // 18432
constexpr int STAGE = B_OFF + BN * ROWB;  // 36864
constexpr int NSTAGES = 3;
constexpr int SMEM_TOTAL = NSTAGES * STAGE;  // 110592 -> 2 CTAs/SM

__device__ __forceinline__ uint32_t smem_u32(const void* p) {
    uint32_t a;
    asm("{ .reg .u64 t; cvta.to.shared.u64 t, %1; cvt.u32.u64 %0, t; }"
        : "=r"(a) : "l"(p));
    return a;
}
__device__ __forceinline__ void cp16(uint32_t dst, const void* src) {
    asm volatile("cp.async.cg.shared.global [%0], [%1], 16;"
                 :: "r"(dst), "l"(src) : "memory");
}
#define CP_COMMIT() asm volatile("cp.async.commit_group;" ::: "memory")
#define CP_WAIT(n)  asm volatile("cp.async.wait_group %0;" :: "n"(n) : "memory")

__device__ __forceinline__ void ldsm_x4(uint32_t* r, uint32_t addr) {
    asm volatile("ldmatrix.sync.aligned.m8n8.x4.shared.b16 {%0,%1,%2,%3}, [%4];"
                 : "=r"(r[0]), "=r"(r[1]), "=r"(r[2]), "=r"(r[3]) : "r"(addr));
}
__device__ __forceinline__ void mma_fp16(float* c, const uint32_t* a,
                                         const uint32_t* b) {
    asm volatile(
        "mma.sync.aligned.m16n8k16.row.col.f32.f16.f16.f32 "
        "{%0,%1,%2,%3}, {%4,%5,%6,%7}, {%8,%9}, {%0,%1,%2,%3};"
        : "+f"(c[0]), "+f"(c[1]), "+f"(c[2]), "+f"(c[3])
        : "r"(a[0]), "r"(a[1]), "r"(a[2]), "r"(a[3]), "r"(b[0]), "r"(b[1]));
}

// ---- pre-pass: x -> fp16 ----
__global__ __launch_bounds__(256)
void convert_x_kernel(const float* __restrict__ X, long total4) {
    long i = (long)blockIdx.x * blockDim.x + threadIdx.x;
    if (i >= total4) return;
    float4 v = reinterpret_cast<const float4*>(X)[i];
    __half2* H = reinterpret_cast<__half2*>(g_X);
    H[2 * i]     = __floats2half2_rn(v.x, v.y);
    H[2 * i + 1] = __floats2half2_rn(v.z, v.w);
}

// ---- pre-pass: dequant W (int4, group scale/zp) -> fp16 ----
__global__ __launch_bounds__(256)
void convert_w_kernel(const int* __restrict__ QW, const float* __restrict__ SC,
                      const float* __restrict__ ZP, int wordsPerRow, int nGroups,
                      long totalWords) {
    long i = (long)blockIdx.x * blockDim.x + threadIdx.x;
    if (i >= totalWords) return;
    int n = (int)(i / wordsPerRow);
    int w = (int)(i % wordsPerRow);
    int g = (w * 8) >> 7;  // group_size 128 = 16 int32 words
    float s = SC[(size_t)n * nGroups + g];
    float z = ZP[(size_t)n * nGroups + g];
    float szn = -s * z;
    unsigned q = (unsigned)QW[i];
    __half2 h[4];
#pragma unroll
    for (int j = 0; j < 4; j++) {
        float f0 = fmaf(s, (float)((q >> (8 * j)) & 0xFu), szn);
        float f1 = fmaf(s, (float)((q >> (8 * j + 4)) & 0xFu), szn);
        h[j] = __floats2half2_rn(f0, f1);
    }
    reinterpret_cast<uint2*>(g_W)[2 * i]     = *reinterpret_cast<uint2*>(&h[0]);
    reinterpret_cast<uint2*>(g_W)[2 * i + 1] = *reinterpret_cast<uint2*>(&h[2]);
}

// ---- main GEMM: 128x128 CTA, BK=64, 8 warps (2x4), warp tile 64x32 ----
__global__ __launch_bounds__(THREADS, 2)
void gemm_kernel(const float* __restrict__ BIAS, float* __restrict__ Y,
                 int M, int N, int K) {
    extern __shared__ char smem[];
    const uint32_t su = smem_u32(smem);
    const int tid  = threadIdx.x;
    const int lane = tid & 31;
    const int wid  = tid >> 5;
    const int bm = blockIdx.y * BM;
    const int bn = blockIdx.x * BN;
    const int mw = (wid >> 2) * 64;   // 2 warps along m
    const int nw = (wid & 3) * 32;    // 4 warps along n

    auto load_stage = [&](int s, int t) {
        const uint32_t sb = su + s * STAGE;
        const size_t k0 = (size_t)t * BK;
#pragma unroll
        for (int j = 0; j < 4; j++) {  // A: 128 rows x 8 x 16B
            int idx = tid + j * THREADS;
            int r = idx >> 3, c = idx & 7;
            cp16(sb + A_OFF + (uint32_t)(r * ROWB + c * 16),
                 (const char*)(g_X + (size_t)(bm + r) * K + k0) + c * 16);
        }
#pragma unroll
        for (int j = 0; j < 4; j++) {  // B: 128 rows x 8 x 16B
            int idx = tid + j * THREADS;
            int r = idx >> 3, c = idx & 7;
            cp16(sb + B_OFF + (uint32_t)(r * ROWB + c * 16),
                 (const char*)(g_W + (size_t)(bn + r) * K + k0) + c * 16);
        }
        CP_COMMIT();
    };

    float acc[4][4][4];
#pragma unroll
    for (int i = 0; i < 4; i++)
#pragma unroll
        for (int j = 0; j < 4; j++)
#pragma unroll
            for (int c = 0; c < 4; c++) acc[i][j][c] = 0.f;

    const int T = K / BK;  // 64
    load_stage(0, 0);
    load_stage(1, 1);

    // per-thread invariant ldmatrix address components
    const uint32_t a_base = (uint32_t)(((lane & 7) + ((lane >> 3) & 1) * 8
                                        + mw) * ROWB
                                       + ((lane >> 4) & 1) * 16) + A_OFF;
    const uint32_t b_base = (uint32_t)(((lane & 7) + ((lane >> 4) & 1) * 8
                                        + nw) * ROWB
                                       + ((lane >> 3) & 1) * 16) + B_OFF;

    uint32_t afr[2][4][4], bfr[2][2][4];

    for (int t = 0; t < T; t++) {
        // In-flight groups: {t, t+1}; wait <=1 completes group t.
        CP_WAIT(1);
        __syncthreads();

        // Issue load(t+2) into stage (t+2)%3 == (t-1)%3 (readers passed
        // the barrier). Empty commits keep depth uniform.
        if (t + 2 < T) load_stage((t + 2) % 3, t + 2);
        else           CP_COMMIT();

        const uint32_t sb = su + (t % 3) * STAGE;
        const uint32_t sa = sb + a_base;
        const uint32_t sbb = sb + b_base;

        // frag prologue: kk = 0 into buffer 0
#pragma unroll
        for (int ms = 0; ms < 4; ms++)
            ldsm_x4(afr[0][ms], sa + (uint32_t)(ms * 16 * ROWB));
#pragma unroll
        for (int ns = 0; ns < 2; ns++)
            ldsm_x4(bfr[0][ns], sbb + (uint32_t)(ns * 16 * ROWB));

#pragma unroll
        for (int kk = 0; kk < BK / 16; kk++) {
            const int cur = kk & 1, nxt = cur ^ 1;
            if (kk < BK / 16 - 1) {
                const uint32_t kb = (uint32_t)((kk + 1) * 32);
#pragma unroll
                for (int ms = 0; ms < 4; ms++)
                    ldsm_x4(afr[nxt][ms], sa + (uint32_t)(ms * 16 * ROWB) + kb);
#pragma unroll
                for (int ns = 0; ns < 2; ns++)
                    ldsm_x4(bfr[nxt][ns], sbb + (uint32_t)(ns * 16 * ROWB) + kb);
            }
#pragma unroll
            for (int ms = 0; ms < 4; ms++)
#pragma unroll
                for (int n8 = 0; n8 < 4; n8++)
                    mma_fp16(acc[ms][n8], afr[cur][ms],
                             &bfr[cur][n8 >> 1][(n8 & 1) * 2]);
        }
    }

    // epilogue: fused bias, float2 stores
#pragma unroll
    for (int n8 = 0; n8 < 4; n8++) {
        const int n0 = bn + nw + n8 * 8 + 2 * (lane & 3);
        const float bv0 = BIAS[n0];
        const float bv1 = BIAS[n0 + 1];
#pragma unroll
        for (int ms = 0; ms < 4; ms++) {
            const int m0 = bm + mw + ms * 16 + (lane >> 2);
            float2 v;
            v.x = acc[ms][n8][0] + bv0;
            v.y = acc[ms][n8][1] + bv1;
            *reinterpret_cast<float2*>(Y + (size_t)m0 * N + n0) = v;
            v.x = acc[ms][n8][2] + bv0;
            v.y = acc[ms][n8][3] + bv1;
            *reinterpret_cast<float2*>(Y + (size_t)(m0 + 8) * N + n0) = v;
        }
    }
}

}  // namespace

extern "C" void kernel_launch(void* const* d_in, const int* in_sizes, int n_in,
                              void* d_out, int out_size) {
    const float* x    = (const float*)d_in[0];
    const int*   qw   = (const int*)d_in[1];
    const float* sc   = (const float*)d_in[2];
    const float* zp   = (const float*)d_in[3];
    const float* bias = (const float*)d_in[4];
    float* y = (float*)d_out;

    const int N = in_sizes[4];
    const long long K = ((long long)in_sizes[1] * 8) / N;
    const long long M = (long long)in_sizes[0] / K;

    cudaFuncSetAttribute(gemm_kernel, cudaFuncAttributeMaxDynamicSharedMemorySize,
                         SMEM_TOTAL);

    {   // x -> fp16
        long total4 = (long)M * K / 4;
        int blocks = (int)((total4 + 255) / 256);
        convert_x_kernel<<<blocks, 256>>>(x, total4);
    }
    {   // dequant W -> fp16
        int wordsPerRow = (int)(K / 8);
        int nGroups = (int)(K / 128);
        long totalWords = (long)N * wordsPerRow;
        int blocks = (int)((totalWords + 255) / 256);
        convert_w_kernel<<<blocks, 256>>>(qw, sc, zp, wordsPerRow, nGroups, totalWords);
    }
    {
        dim3 grid((unsigned)(N / BN), (unsigned)(M / BM));
        gemm_kernel<<<grid, THREADS, SMEM_TOTAL>>>(bias, y, (int)M, N, (int)K);
    }
}